// round 12
// baseline (speedup 1.0000x reference)
#include <cuda_runtime.h>
#include <math.h>

#define Bn 8
#define Sn 2048
#define Dn 2048
#define SMASK 2047
#define IR2 0.70710678118654752f
#define C22 0.35355339059327379f
#define EPSF 1e-8f
#define CFLF 0.4f
#define SQRTD 45.254833995939045f
#define MW 32

__device__ float g_rho_raw[Bn * Sn];
__device__ float g_pt[Bn * Sn];
__device__ float g_rhof[Bn * Sn];

// ------------------------------------------------------------------
// Compile-time Leray taps L (101) and L^2 taps M (2*MW+1).
// ------------------------------------------------------------------
struct TapsF { float L[101]; };
struct MTapsF { float M[2 * MW + 1]; };

__host__ __device__ constexpr TapsF makeTapsF() {
  double h[103] = {};
  for (int m = -49; m <= 49; m++) {
    int am = m < 0 ? -m : m;
    double term = 1.0;
    for (int i = 0; i < am; i++) term *= 0.5;
    double acc = 0.0;
    for (int k = am; k <= 49; k += 2) {
      acc += term;
      int j = (k + m) / 2;
      term = term * (double)((k + 1) * (k + 2)) / (4.0 * (double)((j + 1) * (k + 1 - j)));
    }
    h[51 + m] = -0.5 * acc;
  }
  TapsF t{};
  for (int m = -50; m <= 50; m++) {
    double v = 2.0 * h[51 + m] - h[51 + m - 1] - h[51 + m + 1];
    t.L[50 + m] = (float)((m == 0 ? 1.0 : 0.0) + v);
  }
  return t;
}

__host__ __device__ constexpr MTapsF makeM() {
  double h[103] = {};
  for (int m = -49; m <= 49; m++) {
    int am = m < 0 ? -m : m;
    double term = 1.0;
    for (int i = 0; i < am; i++) term *= 0.5;
    double acc = 0.0;
    for (int k = am; k <= 49; k += 2) {
      acc += term;
      int j = (k + m) / 2;
      term = term * (double)((k + 1) * (k + 2)) / (4.0 * (double)((j + 1) * (k + 1 - j)));
    }
    h[51 + m] = -0.5 * acc;
  }
  double L[101] = {};
  for (int m = -50; m <= 50; m++) {
    double v = 2.0 * h[51 + m] - h[51 + m - 1] - h[51 + m + 1];
    L[50 + m] = (m == 0 ? 1.0 : 0.0) + v;
  }
  MTapsF t{};
  for (int m = -MW; m <= MW; m++) {
    double acc = 0.0;
    for (int j = -50; j <= 50; j++) {
      int k = m - j;
      if (k >= -50 && k <= 50) acc += L[50 + j] * L[50 + k];
    }
    t.M[MW + m] = (float)acc;
  }
  return t;
}

// Runtime-indexed copy (argmax correction lookup only).
__constant__ MTapsF MT = makeM();

// ---- Template-unrolled convs: taps folded to FFMA immediates (rt 1). ----
template<int M_>
__device__ __forceinline__ void fmaL(float& acc, float v) {
  if constexpr (M_ >= -50 && M_ <= 50) {
    constexpr float t = makeTapsF().L[50 + M_];
    acc = fmaf(t, v, acc);
  }
}
template<int M_>
__device__ __forceinline__ void fmaM(float& acc, float v) {
  if constexpr (M_ >= -MW && M_ <= MW) {
    constexpr float t = makeM().M[MW + M_];
    acc = fmaf(t, v, acc);
  }
}

template<int J>
__device__ __forceinline__ void convLstep(const float* __restrict__ in, int base, float* o) {
  int p = (base + 4 * J) & SMASK;
  float4 w = *(const float4*)(in + p);
  constexpr int rel = 4 * J - 52;
  fmaL<rel + 0 - 0>(o[0], w.x); fmaL<rel + 0 - 1>(o[1], w.x);
  fmaL<rel + 0 - 2>(o[2], w.x); fmaL<rel + 0 - 3>(o[3], w.x);
  fmaL<rel + 1 - 0>(o[0], w.y); fmaL<rel + 1 - 1>(o[1], w.y);
  fmaL<rel + 1 - 2>(o[2], w.y); fmaL<rel + 1 - 3>(o[3], w.y);
  fmaL<rel + 2 - 0>(o[0], w.z); fmaL<rel + 2 - 1>(o[1], w.z);
  fmaL<rel + 2 - 2>(o[2], w.z); fmaL<rel + 2 - 3>(o[3], w.z);
  fmaL<rel + 3 - 0>(o[0], w.w); fmaL<rel + 3 - 1>(o[1], w.w);
  fmaL<rel + 3 - 2>(o[2], w.w); fmaL<rel + 3 - 3>(o[3], w.w);
}
template<int J>
__device__ __forceinline__ void convLloop(const float* __restrict__ in, int base, float* o) {
  if constexpr (J < 27) { convLstep<J>(in, base, o); convLloop<J + 1>(in, base, o); }
}
__device__ __forceinline__ void convL4(const float* __restrict__ in, int q, float* o) {
  o[0] = o[1] = o[2] = o[3] = 0.f;
  convLloop<0>(in, q + (Sn - 52), o);
}

template<int J>
__device__ __forceinline__ void convMstep(const float* __restrict__ in, int base, float* o) {
  int p = (base + 4 * J) & SMASK;
  float4 w = *(const float4*)(in + p);
  constexpr int rel = 4 * J - MW;
  fmaM<rel + 0 - 0>(o[0], w.x); fmaM<rel + 0 - 1>(o[1], w.x);
  fmaM<rel + 0 - 2>(o[2], w.x); fmaM<rel + 0 - 3>(o[3], w.x);
  fmaM<rel + 1 - 0>(o[0], w.y); fmaM<rel + 1 - 1>(o[1], w.y);
  fmaM<rel + 1 - 2>(o[2], w.y); fmaM<rel + 1 - 3>(o[3], w.y);
  fmaM<rel + 2 - 0>(o[0], w.z); fmaM<rel + 2 - 1>(o[1], w.z);
  fmaM<rel + 2 - 2>(o[2], w.z); fmaM<rel + 2 - 3>(o[3], w.z);
  fmaM<rel + 3 - 0>(o[0], w.w); fmaM<rel + 3 - 1>(o[1], w.w);
  fmaM<rel + 3 - 2>(o[2], w.w); fmaM<rel + 3 - 3>(o[3], w.w);
}
template<int J>
__device__ __forceinline__ void convMloop(const float* __restrict__ in, int base, float* o) {
  if constexpr (J < 17) { convMstep<J>(in, base, o); convMloop<J + 1>(in, base, o); }
}
__device__ __forceinline__ void convM4(const float* __restrict__ in, int q, float* o) {
  o[0] = o[1] = o[2] = o[3] = 0.f;
  convMloop<0>(in, q + (Sn - MW), o);
}

// ------------------------------------------------------------------
// Kernel A: proven 62-reg version.
// ------------------------------------------------------------------
__global__ void __launch_bounds__(256) kA(const float* __restrict__ x,
                                          const float* __restrict__ w) {
  int blk = blockIdx.x;
  int b = blk >> 8, k = blk & 255;
  const float4* base = (const float4*)(x + ((size_t)b * Sn + (size_t)k * 8) * Dn);
  const float4* w4 = (const float4*)w;

  float acc[16];
#pragma unroll
  for (int q = 0; q < 16; q++) acc[q] = 0.f;

  for (int c = threadIdx.x; c < Dn / 4; c += 256) {
    float4 xr[8];
#pragma unroll
    for (int j = 0; j < 8; j++) xr[j] = __ldcs(base + j * (Dn / 4) + c);
    float4 wv = w4[c];
#pragma unroll
    for (int comp = 0; comp < 4; comp++) {
      float v0 = ((const float*)&xr[0])[comp];
      float v1 = ((const float*)&xr[1])[comp];
      float v2 = ((const float*)&xr[2])[comp];
      float v3 = ((const float*)&xr[3])[comp];
      float v4 = ((const float*)&xr[4])[comp];
      float v5 = ((const float*)&xr[5])[comp];
      float v6 = ((const float*)&xr[6])[comp];
      float v7 = ((const float*)&xr[7])[comp];
      float wc = ((const float*)&wv)[comp];
      float e0 = v0 + v1, e1 = v2 + v3, e2 = v4 + v5, e3 = v6 + v7;
      float d10 = v0 - v1, d11 = v2 - v3, d12 = v4 - v5, d13 = v6 - v7;
      float a20 = e0 + e1, a21 = e2 + e3;
      float d20 = e0 - e1, d21 = e2 - e3;
      float a3 = a20 + a21, d3 = a20 - a21;
      acc[0] += a3 * a3;   acc[1] += d3 * d3;
      acc[2] += d20 * d20; acc[3] += d21 * d21;
      acc[4] += d10 * d10; acc[5] += d11 * d11;
      acc[6] += d12 * d12; acc[7] += d13 * d13;
      acc[8]  += v0 * wc; acc[9]  += v1 * wc; acc[10] += v2 * wc; acc[11] += v3 * wc;
      acc[12] += v4 * wc; acc[13] += v5 * wc; acc[14] += v6 * wc; acc[15] += v7 * wc;
    }
  }

  __shared__ float red[128];
  int lane = threadIdx.x & 31, wid = threadIdx.x >> 5;
#pragma unroll
  for (int q = 0; q < 16; q++) {
    float val = acc[q];
#pragma unroll
    for (int o = 16; o; o >>= 1) val += __shfl_xor_sync(0xffffffffu, val, o);
    if (lane == 0) red[q * 8 + wid] = val;
  }
  __syncthreads();
  if (threadIdx.x < 16) {
    float s2 = 0.f;
#pragma unroll
    for (int ww = 0; ww < 8; ww++) s2 += red[threadIdx.x * 8 + ww];
    int bs = b * Sn;
    int t = threadIdx.x;
    if (t == 0)      g_rho_raw[bs + k]                      = sqrtf(s2) * C22;
    else if (t == 1) g_rho_raw[bs + 256 + k]                = sqrtf(s2) * C22;
    else if (t < 4)  g_rho_raw[bs + 512 + 2 * k + (t - 2)]  = sqrtf(s2) * 0.5f;
    else if (t < 8)  g_rho_raw[bs + 1024 + 4 * k + (t - 4)] = sqrtf(s2) * IR2;
    else             g_pt[bs + 8 * k + (t - 8)] = s2;
  }
}

// ------------------------------------------------------------------
// Reductions for 16 warps.
// ------------------------------------------------------------------
__device__ __forceinline__ void redStoreSum(float v, float* buf, int lane, int wid) {
#pragma unroll
  for (int o = 16; o; o >>= 1) v += __shfl_xor_sync(0xffffffffu, v, o);
  if (lane == 0) buf[wid] = v;
}
__device__ __forceinline__ float readSum16(const float* buf, int lane) {
  float v = buf[lane & 15];
#pragma unroll
  for (int o = 8; o; o >>= 1) v += __shfl_xor_sync(0xffffffffu, v, o);
  return v;
}
__device__ __forceinline__ void redStoreMaxIdx(float v, int idx, float* bv, int* bi,
                                               int lane, int wid) {
#pragma unroll
  for (int o = 16; o; o >>= 1) {
    float ov = __shfl_xor_sync(0xffffffffu, v, o);
    int oi = __shfl_xor_sync(0xffffffffu, idx, o);
    if (ov > v || (ov == v && oi < idx)) { v = ov; idx = oi; }
  }
  if (lane == 0) { bv[wid] = v; bi[wid] = idx; }
}
__device__ __forceinline__ float readMax16(const float* bv, const int* bi, int lane,
                                           int* oi) {
  float v = bv[lane & 15]; int idx = bi[lane & 15];
#pragma unroll
  for (int o = 8; o; o >>= 1) {
    float ov = __shfl_xor_sync(0xffffffffu, v, o);
    int oi2 = __shfl_xor_sync(0xffffffffu, idx, o);
    if (ov > v || (ov == v && oi2 < idx)) { v = ov; idx = oi2; }
  }
  *oi = idx;
  return v;
}

// ------------------------------------------------------------------
// Kernel B
// ------------------------------------------------------------------
__global__ void __launch_bounds__(512, 1) kB(const float* __restrict__ phi_g) {
  int b = blockIdx.x;
  extern __shared__ float sm[];
  float* phi_s = sm + 0 * Sn;
  float* vv   = sm + 1 * Sn;
  float* rb0  = sm + 2 * Sn;
  float* rb1  = sm + 3 * Sn;
  float* up0  = sm + 4 * Sn;
  float* upA  = sm + 5 * Sn;
  float* upB  = sm + 6 * Sn;
  float* z1   = sm + 7 * Sn;
  float* z2   = sm + 8 * Sn;
  float* z3   = sm + 9 * Sn;
  float* z4   = sm + 10 * Sn;
  float* grA  = sm + 11 * Sn;
  float* grB  = sm + 12 * Sn;
  float* gup  = sm + 13 * Sn;
  float* red  = sm + 14 * Sn;
  float* redMax = red;
  int*   redIdx = (int*)(red + 32);
  float* redSS  = red + 64;
  float* dotB0  = red + 192;
  float* dotB1  = red + 224;
  float* redPart = red + 256;
  float* redR   = red + 288;
  float* redF   = red + 320;

  const int tid = threadIdx.x;
  const int lane = tid & 31, wid = tid >> 5;
  const int q = 4 * tid;
  const int pm1 = (q + SMASK) & SMASK;
  const int pp4 = (q + 4) & SMASK;

  // ---- I1 ----
  {
    float4 ph = *(const float4*)(phi_g + q);
    *(float4*)(phi_s + q) = ph;
    float4 rr = *(const float4*)(g_rho_raw + b * Sn + q);
    rr.x += EPSF; rr.y += EPSF; rr.z += EPSF; rr.w += EPSF;
    *(float4*)(rb0 + q) = rr;
  }
  if (tid < 256) {
    const float* p = g_pt + b * Sn + tid * 8;
    float v0 = p[0], v1 = p[1], v2 = p[2], v3 = p[3];
    float v4 = p[4], v5 = p[5], v6 = p[6], v7 = p[7];
    float e0 = v0 + v1, e1 = v2 + v3, e2 = v4 + v5, e3 = v6 + v7;
    float d10 = v0 - v1, d11 = v2 - v3, d12 = v4 - v5, d13 = v6 - v7;
    float a20 = e0 + e1, a21 = e2 + e3;
    float d20 = e0 - e1, d21 = e2 - e3;
    float a3 = a20 + a21, d3 = a20 - a21;
    vv[tid]               = fabsf(a3) * C22 * SQRTD;
    vv[256 + tid]         = fabsf(d3) * C22 * SQRTD;
    vv[512 + 2 * tid]     = fabsf(d20) * 0.5f * SQRTD;
    vv[512 + 2 * tid + 1] = fabsf(d21) * 0.5f * SQRTD;
    vv[1024 + 4 * tid]     = fabsf(d10) * IR2 * SQRTD;
    vv[1024 + 4 * tid + 1] = fabsf(d11) * IR2 * SQRTD;
    vv[1024 + 4 * tid + 2] = fabsf(d12) * IR2 * SQRTD;
    vv[1024 + 4 * tid + 3] = fabsf(d13) * IR2 * SQRTD;
  }
  __syncthreads();
  // ---- I2 ----
  float4 rawq = *(const float4*)(vv + q);
  float rawp = vv[pp4];
  {
    float4 rq = *(const float4*)(rb0 + q);
    redStoreSum((rq.x + rq.y) + (rq.z + rq.w), redF, lane, wid);
    redStoreSum((rawq.x + rawq.y) + (rawq.z + rawq.w) + 4.f * EPSF, redR, lane, wid);
  }
  __syncthreads();
  // ---- I3 ----
  float vq0, vq1, vq2, vq3, sd0, sd1, sd2, sd3;
  {
    float inv = 1.f / readSum16(redR, lane);
    vq0 = (rawq.x + EPSF) * inv; vq1 = (rawq.y + EPSF) * inv;
    vq2 = (rawq.z + EPSF) * inv; vq3 = (rawq.w + EPSF) * inv;
    *(float4*)(vv + q) = make_float4(vq0, vq1, vq2, vq3);
    sd0 = (1.f - vq0) * 0.125f; sd1 = (1.f - vq1) * 0.125f;
    sd2 = (1.f - vq2) * 0.125f; sd3 = (1.f - vq3) * 0.125f;
    float4 g = make_float4((rawq.y - rawq.x) * inv, (rawq.z - rawq.y) * inv,
                           (rawq.w - rawq.z) * inv, (rawp - rawq.w) * inv);
    *(float4*)(gup + q) = g;
  }
  __syncthreads();
  // ---- I4b ----
  {
    float c[4];
    convL4(gup, q, c);
    *(float4*)(up0 + q) = make_float4(c[0], c[1], c[2], c[3]);
    float mv = -1.f; int mi = 0;
#pragma unroll
    for (int e = 0; e < 4; e++) {
      float a = fabsf(c[e]);
      if (a > mv) { mv = a; mi = q + e; }
    }
    redStoreMaxIdx(mv, mi, redMax, redIdx, lane, wid);
  }
  __syncthreads();

  float dt0 = 0.f; int imax0 = 0;
  float invRho = 0.f, Rho = 0.f, E = 0.f;
  float* rz = rb0;
  float* rzo = rb1;

  for (int ko = 0; ko < 3; ko++) {
    // ---- PR1 ----
    {
      if (ko == 0) {
        int mi; float m = readMax16(redMax, redIdx, lane, &mi);
        dt0 = CFLF / (m + EPSF); imax0 = mi;
      }
      float invR = 1.f / readSum16(redF, lane);
      float4 rq = *(const float4*)(rz + q);
      float4 ph = *(const float4*)(phi_s + q);
      float w0 = rq.x * invR, w1 = rq.y * invR, w2 = rq.z * invR, w3 = rq.w * invR;
      w0 = w0 * expf(-0.1f * (ph.x + logf(w0))) + EPSF;
      w1 = w1 * expf(-0.1f * (ph.y + logf(w1))) + EPSF;
      w2 = w2 * expf(-0.1f * (ph.z + logf(w2))) + EPSF;
      w3 = w3 * expf(-0.1f * (ph.w + logf(w3))) + EPSF;
      *(float4*)(rz + q) = make_float4(w0, w1, w2, w3);
      redStoreSum((w0 + w1) + (w2 + w3), redR, lane, wid);
    }
    __syncthreads();

    float dt = 0.f; int imax = 0;

    for (int it = 0; it < 5; it++) {
      const float* uin = (it == 0) ? up0 : ((it & 1) ? upB : upA);
      float* uout = (it & 1) ? upA : upB;
      float part = 0.f;
      float um, u0, u1, u2, u3, uImaxV;

      // ---- FF: fused forward horizon ----
      {
        if (it == 0) {
          Rho = readSum16(redR, lane); invRho = 1.f / Rho;
          E = EPSF * Rho;
          dt = dt0; imax = imax0;
        } else {
          float m = readMax16(redMax, redIdx, lane, &imax);
          dt = CFLF / (m + EPSF);
        }
        float U[12], L[12];
        {
          float4 t = *(const float4*)(uin + ((q + Sn - 4) & SMASK));
          U[0] = t.x; U[1] = t.y; U[2] = t.z; U[3] = t.w;
        }
        {
          float4 t = *(const float4*)(uin + q);
          U[4] = t.x; U[5] = t.y; U[6] = t.z; U[7] = t.w;
        }
        {
          float4 t = *(const float4*)(uin + ((q + 4) & SMASK));
          U[8] = t.x; U[9] = t.y; U[10] = t.z; U[11] = t.w;
        }
        {
          float4 t = *(const float4*)(rz + ((q + Sn - 4) & SMASK));
          L[0] = t.x; L[1] = t.y; L[2] = t.z; L[3] = t.w;
        }
        {
          float4 t = *(const float4*)(rz + q);
          L[4] = t.x; L[5] = t.y; L[6] = t.z; L[7] = t.w;
        }
        {
          float4 t = *(const float4*)(rz + ((q + 4) & SMASK));
          L[8] = t.x; L[9] = t.y; L[10] = t.z; L[11] = t.w;
        }
        um = U[3]; u0 = U[4]; u1 = U[5]; u2 = U[6]; u3 = U[7];
        uImaxV = uin[imax];
        *(float4*)(gup + q) = make_float4(0.f, 0.f, 0.f, 0.f);
        float* zArr[4] = {z1, z2, z3, z4};
#pragma unroll
        for (int h = 0; h < 4; h++) {
          const int lo = 1 + h, hi = 10 - h;
          float F[11], Y[12];
#pragma unroll
          for (int i = 0; i < 11; i++)
            if (i >= lo - 1 && i <= hi)
              F[i] = U[i] > 0.f ? U[i] * L[i] : U[i] * L[i + 1];
#pragma unroll
          for (int i = 0; i < 12; i++)
            if (i >= lo && i <= hi) Y[i] = L[i] - dt * (F[i] - F[i - 1]);
          *(float4*)(zArr[h] + q) = make_float4(Y[4], Y[5], Y[6], Y[7]);
#pragma unroll
          for (int i = 0; i < 12; i++)
            if (i >= lo && i <= hi) L[i] = fabsf(Y[i]) + E;
          redStoreSum((L[4] + L[5]) + (L[6] + L[7]), redSS + 32 * h, lane, wid);
          if (h == 3)
            redStoreSum((sd0 * L[4] + sd1 * L[5]) + (sd2 * L[6] + sd3 * L[7]),
                        dotB1, lane, wid);
        }
      }
      __syncthreads();

      // ---- G3..G0 ----
      float S1 = 0.f, S2 = 0.f, S3 = 0.f;
      float iS1 = 0.f, iS2 = 0.f, iS3 = 0.f, iS4 = 0.f;
#pragma unroll
      for (int h = 3; h >= 0; h--) {
        const float* zout = (h == 3) ? z4 : (h == 2 ? z3 : (h == 1 ? z2 : z1));
        const float* zin  = (h == 3) ? z3 : (h == 2 ? z2 : (h == 1 ? z1 : rz));
        const float* grOld = (((h + 1) & 1) ? grB : grA);
        float* grNew = ((h & 1) ? grB : grA);
        const float* dotRd = ((h & 1) ? dotB1 : dotB0);
        float* dotWr = ((h & 1) ? dotB0 : dotB1);

        if (h == 3) {
          S1 = readSum16(redSS + 0, lane);  iS1 = 1.f / S1;
          S2 = readSum16(redSS + 32, lane); iS2 = 1.f / S2;
          S3 = readSum16(redSS + 64, lane); iS3 = 1.f / S3;
          iS4 = 1.f / readSum16(redSS + 96, lane);
        }
        const float iSoutN = (h == 3) ? iS4 : (h == 2 ? iS3 : (h == 1 ? iS2 : iS1));
        const float Sh     = (h == 3) ? S3 : (h == 2 ? S2 : (h == 1 ? S1 : Rho));
        const float iSh    = (h == 3) ? iS3 : (h == 2 ? iS2 : (h == 1 ? iS1 : invRho));
        const float gwScale = Sh * iSoutN;
        float dotv = readSum16(dotRd, lane) * iSoutN;

        float gy[6];
        {
          float yv[6], gin[6];
          yv[0] = zout[pm1]; yv[5] = zout[pp4];
          float4 zq = *(const float4*)(zout + q);
          yv[1] = zq.x; yv[2] = zq.y; yv[3] = zq.z; yv[4] = zq.w;
          if (h == 3) {
            gin[0] = (1.f - vv[pm1]) * 0.125f;
            gin[5] = (1.f - vv[pp4]) * 0.125f;
            gin[1] = sd0; gin[2] = sd1; gin[3] = sd2; gin[4] = sd3;
          } else {
            gin[0] = grOld[pm1]; gin[5] = grOld[pp4];
            float4 gq = *(const float4*)(grOld + q);
            gin[1] = gq.x; gin[2] = gq.y; gin[3] = gq.z; gin[4] = gq.w;
          }
#pragma unroll
          for (int e = 0; e < 6; e++) {
            float gw = (gin[e] - dotv) * gwScale;
            gy[e] = yv[e] > 0.f ? gw : (yv[e] < 0.f ? -gw : 0.f);
          }
        }

        float Lm1 = zin[pm1], Lp = zin[pp4];
        float4 ziq = *(const float4*)(zin + q);
        float o0, o1, o2, o3;
        if (h == 0) {
          o0 = ziq.x; o1 = ziq.y; o2 = ziq.z; o3 = ziq.w;
        } else {
          o0 = fabsf(ziq.x) + E; o1 = fabsf(ziq.y) + E;
          o2 = fabsf(ziq.z) + E; o3 = fabsf(ziq.w) + E;
          Lm1 = fabsf(Lm1) + E; Lp = fabsf(Lp) + E;
        }
        float r0 = o0 * iSh, r1 = o1 * iSh, r2 = o2 * iSh, r3 = o3 * iSh;
        float rp = Lp * iSh;

        float Ftm = um > 0.f ? um * Lm1 : um * o0;
        float F0 = u0 > 0.f ? u0 * o0 : u0 * o1;
        float F1 = u1 > 0.f ? u1 * o1 : u1 * o2;
        float F2 = u2 > 0.f ? u2 * o2 : u2 * o3;
        float F3 = u3 > 0.f ? u3 * o3 : u3 * Lp;
        part += iSh * (gy[1] * (Ftm - F0) + gy[2] * (F0 - F1) +
                       gy[3] * (F1 - F2) + gy[4] * (F2 - F3));
        float gFs0 = dt * (gy[2] - gy[1]);
        float gFs1 = dt * (gy[3] - gy[2]);
        float gFs2 = dt * (gy[4] - gy[3]);
        float gFs3 = dt * (gy[5] - gy[4]);
        float gFm0 = dt * (gy[1] - gy[0]);
        {
          float4 gq = *(const float4*)(gup + q);
          gq.x += gFs0 * (u0 > 0.f ? r0 : r1);
          gq.y += gFs1 * (u1 > 0.f ? r1 : r2);
          gq.z += gFs2 * (u2 > 0.f ? r2 : r3);
          gq.w += gFs3 * (u3 > 0.f ? r3 : rp);
          *(float4*)(gup + q) = gq;
        }
        if (h > 0) {
          float ngr0 = gy[1] + (u0 > 0.f ? u0 * gFs0 : 0.f) + (um > 0.f ? 0.f : um * gFm0);
          float ngr1 = gy[2] + (u1 > 0.f ? u1 * gFs1 : 0.f) + (u0 > 0.f ? 0.f : u0 * gFs0);
          float ngr2 = gy[3] + (u2 > 0.f ? u2 * gFs2 : 0.f) + (u1 > 0.f ? 0.f : u1 * gFs1);
          float ngr3 = gy[4] + (u3 > 0.f ? u3 * gFs3 : 0.f) + (u2 > 0.f ? 0.f : u2 * gFs2);
          *(float4*)(grNew + q) = make_float4(ngr0, ngr1, ngr2, ngr3);
          redStoreSum((ngr0 * o0 + ngr1 * o1) + (ngr2 * o2 + ngr3 * o3), dotWr, lane, wid);
        } else {
          redStoreSum(part, redPart, lane, wid);
        }
        __syncthreads();
      }

      // ---- PE' ----
      {
        float gdt = readSum16(redPart, lane);
        float gm = gdt * (-dt * dt * (1.0f / CFLF));
        float sg = uImaxV > 0.f ? 1.f : (uImaxV < 0.f ? -1.f : 0.f);
        float c[4];
        convM4(gup, q, c);
        float uq[4] = {u0, u1, u2, u3};
        float mv = -1.f; int mi = 0;
#pragma unroll
        for (int e = 0; e < 4; e++) {
          int dd = ((imax - (q + e) + 1024) & SMASK) - 1024;
          float corr = (dd >= -MW && dd <= MW) ? gm * sg * MT.M[MW + dd] : 0.f;
          float n = uq[e] - 0.1f * (c[e] + corr);
          c[e] = n;
          float a = fabsf(n);
          if (a > mv) { mv = a; mi = q + e; }
        }
        *(float4*)(uout + q) = make_float4(c[0], c[1], c[2], c[3]);
        redStoreMaxIdx(mv, mi, redMax, redIdx, lane, wid);
      }
      __syncthreads();
    }

    // ---- PF2 ----
    {
      int mi; float m = readMax16(redMax, redIdx, lane, &mi);
      float dtf = CFLF / (m + EPSF);
      float kap = (ko == 0) ? 0.01f : ((ko == 1) ? 0.005f : 0.0f);
      const float* uf = upB;
      float rm = rz[pm1] * invRho, rp = rz[pp4] * invRho;
      float4 rq = *(const float4*)(rz + q);
      float r0 = rq.x * invRho, r1 = rq.y * invRho, r2 = rq.z * invRho, r3 = rq.w * invRho;
      float um2 = uf[pm1];
      float4 uq = *(const float4*)(uf + q);
      float Fm = um2 > 0.f ? um2 * rm : um2 * r0;
      float F0 = uq.x > 0.f ? uq.x * r0 : uq.x * r1;
      float F1 = uq.y > 0.f ? uq.y * r1 : uq.y * r2;
      float F2 = uq.z > 0.f ? uq.z * r2 : uq.z * r3;
      float F3 = uq.w > 0.f ? uq.w * r3 : uq.w * rp;
      float y0 = r0 - dtf * (F0 - Fm) + kap * dtf * (r1 + rm - 2.f * r0);
      float y1 = r1 - dtf * (F1 - F0) + kap * dtf * (r2 + r0 - 2.f * r1);
      float y2 = r2 - dtf * (F2 - F1) + kap * dtf * (r3 + r1 - 2.f * r2);
      float y3 = r3 - dtf * (F3 - F2) + kap * dtf * (rp + r2 - 2.f * r3);
      float o0 = fabsf(y0) + EPSF, o1 = fabsf(y1) + EPSF;
      float o2 = fabsf(y2) + EPSF, o3 = fabsf(y3) + EPSF;
      *(float4*)(rzo + q) = make_float4(o0, o1, o2, o3);
      redStoreSum((o0 + o1) + (o2 + o3), redF, lane, wid);
    }
    __syncthreads();
    { float* t = rz; rz = rzo; rzo = t; }
  }

  // ---- FO ----
  float t0, t1, t2, t3;
  {
    float invR = 1.f / readSum16(redF, lane);
    float4 rq = *(const float4*)(rz + q);
    t0 = rq.x * invR + 0.1f * vq0;
    t1 = rq.y * invR + 0.1f * vq1;
    t2 = rq.z * invR + 0.1f * vq2;
    t3 = rq.w * invR + 0.1f * vq3;
    redStoreSum((t0 + t1) + (t2 + t3), redR, lane, wid);
  }
  __syncthreads();
  {
    float invSf = 1.f / readSum16(redR, lane);
    *(float4*)(g_rhof + b * Sn + q) =
        make_float4(t0 * invSf, t1 * invSf, t2 * invSf, t3 * invSf);
  }
}

// ------------------------------------------------------------------
// Kernel C
// ------------------------------------------------------------------
__global__ void __launch_bounds__(512) kC(const float* __restrict__ bw,
                                          float* __restrict__ out) {
  int blk = blockIdx.x;
  int b = blk >> 8, k = blk & 255;
  const float* rf = g_rhof + b * Sn;
  float A  = rf[k] * C22;
  float E  = rf[256 + k] * C22;
  float C0 = rf[512 + 2 * k] * 0.5f;
  float C1 = rf[512 + 2 * k + 1] * 0.5f;
  float D0 = rf[1024 + 4 * k] * IR2;
  float D1 = rf[1024 + 4 * k + 1] * IR2;
  float D2 = rf[1024 + 4 * k + 2] * IR2;
  float D3 = rf[1024 + 4 * k + 3] * IR2;

  float s1[8], s2[8], s3[8];
#pragma unroll
  for (int j = 0; j < 8; j++) {
    float Ej = (j < 4) ? E : -E;
    float Cj = (j < 4) ? C0 : C1;
    if ((j & 3) >= 2) Cj = -Cj;
    float Dj = (j >> 1) == 0 ? D0 : ((j >> 1) == 1 ? D1 : ((j >> 1) == 2 ? D2 : D3));
    if (j & 1) Dj = -Dj;
    s1[j] = Ej; s2[j] = Cj; s3[j] = Dj;
  }

  const float4* b0 = (const float4*)bw;
  const float4* b1 = (const float4*)(bw + Dn);
  const float4* b2 = (const float4*)(bw + 2 * Dn);
  const float4* b3 = (const float4*)(bw + 3 * Dn);
  float4* ob = (float4*)(out + ((size_t)b * Sn + (size_t)k * 8) * Dn);

  int c = threadIdx.x;
  float4 w0 = b0[c], w1 = b1[c], w2 = b2[c], w3 = b3[c];
#pragma unroll
  for (int j = 0; j < 8; j++) {
    float4 o;
    o.x = A * w0.x + s1[j] * w1.x + s2[j] * w2.x + s3[j] * w3.x;
    o.y = A * w0.y + s1[j] * w1.y + s2[j] * w2.y + s3[j] * w3.y;
    o.z = A * w0.z + s1[j] * w1.z + s2[j] * w2.z + s3[j] * w3.z;
    o.w = A * w0.w + s1[j] * w1.w + s2[j] * w2.w + s3[j] * w3.w;
    __stcs(ob + j * (Dn / 4) + c, o);
  }
}

// ------------------------------------------------------------------
#define SMEMB ((14 * Sn + 512) * 4)

extern "C" void kernel_launch(void* const* d_in, const int* in_sizes, int n_in,
                              void* d_out, int out_size) {
  const float* x   = (const float*)d_in[0];
  const float* w   = (const float*)d_in[1];
  const float* phi = (const float*)d_in[2];
  const float* bw  = (const float*)d_in[3];
  float* out = (float*)d_out;

  cudaFuncSetAttribute((const void*)kB, cudaFuncAttributeMaxDynamicSharedMemorySize, SMEMB);

  kA<<<Bn * 256, 256>>>(x, w);
  kB<<<Bn, 512, SMEMB>>>(phi);
  kC<<<Bn * 256, 512>>>(bw, out);
}